// round 16
// baseline (speedup 1.0000x reference)
#include <cuda_runtime.h>
#include <cuda_bf16.h>
#include <cstdint>

// ---------------- problem constants ----------------
#define D      512
#define NTOT   32768            // 8*4096 samples
#define MT     128              // CTA gemm M tile
#define NT     64               // CTA gemm N tile
#define KC     64               // k per smem stage (64 bf16 = 128B rows)
#define NSPLIT 9                // 32 tiles * 9 = 288 CTAs <= 296 resident slots
#define TOTCHUNK (NTOT / KC)    // 512 total k-chunks
#define NCTAS  (32 * NSPLIT)    // 288

// ---------------- device scratch (no allocation) ----------------
__device__ __nv_bfloat16 g_Ht[(size_t)D * NTOT];   // 32 MB, K-major transposed hi
__device__ __nv_bfloat16 g_Lt[(size_t)D * NTOT];   // 32 MB, K-major transposed lo
__device__ float  g_c[D * D];                      // C = HH + HL + HL^T
__device__ float  g_ps2[8 * NTOT];                 // per-(dblock,sample) sum x^2
__device__ float  g_ps4[8 * NTOT];                 // per-(dblock,sample) sum x^4
__device__ double g_corr, g_whit;

__device__ __forceinline__ uint32_t smem_to_u32(const void* p) {
    uint32_t a;
    asm("{ .reg .u64 t; cvta.to.shared.u64 t, %1; cvt.u32.u64 %0, t; }" : "=r"(a) : "l"(p));
    return a;
}

// ---------------- kernel 1: transpose + hi/lo split + loss partials + zero ----
__global__ void __launch_bounds__(256) convert_kernel(const float* __restrict__ x) {
    __shared__ float tile[64][65];
    const int n0  = blockIdx.x * 64;
    const int db  = blockIdx.y;
    const int d0  = db * 64;
    const int tid = threadIdx.x;

    if (db == 0) {
        int base = blockIdx.x * 512 + tid;
        g_c[base] = 0.0f;
        g_c[base + 256] = 0.0f;
        if (blockIdx.x == 0 && tid == 0) { g_corr = 0.0; g_whit = 0.0; }
    }

    const int r  = tid >> 4;
    const int c4 = (tid & 15) * 4;
    float s2[4] = {0.f, 0.f, 0.f, 0.f};
    float s4[4] = {0.f, 0.f, 0.f, 0.f};
#pragma unroll
    for (int p = 0; p < 4; ++p) {
        int n = p * 16 + r;
        // streaming load: x is read exactly once
        float4 v = __ldcs(reinterpret_cast<const float4*>(x + (size_t)(n0 + n) * D + d0 + c4));
        tile[n][c4 + 0] = v.x; tile[n][c4 + 1] = v.y;
        tile[n][c4 + 2] = v.z; tile[n][c4 + 3] = v.w;
        float a = v.x * v.x, b = v.y * v.y, c = v.z * v.z, d = v.w * v.w;
        s2[p] += a + b + c + d;
        s4[p] += a * a + b * b + c * c + d * d;
    }
    __syncthreads();
    const int dd = tid >> 2;
    const int nb = (tid & 3) * 16;
    __align__(16) __nv_bfloat16 hi[16];
    __align__(16) __nv_bfloat16 lo[16];
#pragma unroll
    for (int u = 0; u < 16; ++u) {
        float v = tile[nb + u][dd];
        __nv_bfloat16 h = __float2bfloat16(v);
        hi[u] = h;
        lo[u] = __float2bfloat16(v - __bfloat162float(h));
    }
    size_t base = (size_t)(d0 + dd) * NTOT + (size_t)(n0 + nb);
    *reinterpret_cast<uint4*>(&g_Ht[base])     = *reinterpret_cast<uint4*>(hi);
    *reinterpret_cast<uint4*>(&g_Ht[base + 8]) = *reinterpret_cast<uint4*>(hi + 8);
    *reinterpret_cast<uint4*>(&g_Lt[base])     = *reinterpret_cast<uint4*>(lo);
    *reinterpret_cast<uint4*>(&g_Lt[base + 8]) = *reinterpret_cast<uint4*>(lo + 8);

#pragma unroll
    for (int o = 8; o > 0; o >>= 1)
#pragma unroll
        for (int p = 0; p < 4; ++p) {
            s2[p] += __shfl_xor_sync(0xFFFFFFFFu, s2[p], o);
            s4[p] += __shfl_xor_sync(0xFFFFFFFFu, s4[p], o);
        }
    if ((tid & 15) == 0) {
#pragma unroll
        for (int p = 0; p < 4; ++p) {
            int n = n0 + p * 16 + r;
            g_ps2[db * NTOT + n] = s2[p];
            g_ps4[db * NTOT + n] = s4[p];
        }
    }
}

// ---------------- kernel 2: mma.sync gram + fused loss reduction -------------
// Prologue (overlapped with stage-0 cp.async): each CTA reduces ~114 samples
// of the loss partials and REDGs two fp64 sums.
// Mainloop: R13 config. Epilogue: g_c[i][j] += HH+HL ; g_c[j][i] += HL
#define STAGE_BYTES 32768
#define A_AREA  0
#define BH_AREA 16384
#define BL_AREA 24576
#define SMEM_BYTES (2 * STAGE_BYTES)

__device__ __forceinline__ uint32_t sw128(uint32_t off) {
    return off ^ ((off >> 3) & 0x70);
}
__device__ __forceinline__ void cp16(uint32_t saddr, const void* gaddr) {
    asm volatile("cp.async.cg.shared.global [%0], [%1], 16;" :: "r"(saddr), "l"(gaddr));
}
__device__ __forceinline__ void cp_commit() {
    asm volatile("cp.async.commit_group;" ::: "memory");
}
template <int N>
__device__ __forceinline__ void cp_wait() {
    asm volatile("cp.async.wait_group %0;" :: "n"(N) : "memory");
}
__device__ __forceinline__ void ldsm_x4(uint32_t* r, uint32_t addr) {
    asm volatile("ldmatrix.sync.aligned.m8n8.x4.shared.b16 {%0,%1,%2,%3}, [%4];"
                 : "=r"(r[0]), "=r"(r[1]), "=r"(r[2]), "=r"(r[3]) : "r"(addr));
}
__device__ __forceinline__ void mma_bf16(float* c, const uint32_t* a, const uint32_t* b) {
    asm volatile(
        "mma.sync.aligned.m16n8k16.row.col.f32.bf16.bf16.f32 "
        "{%0,%1,%2,%3}, {%4,%5,%6,%7}, {%8,%9}, {%0,%1,%2,%3};"
        : "+f"(c[0]), "+f"(c[1]), "+f"(c[2]), "+f"(c[3])
        : "r"(a[0]), "r"(a[1]), "r"(a[2]), "r"(a[3]), "r"(b[0]), "r"(b[1]));
}
__device__ __forceinline__ double shfl_xor_d(double v, int m) {
    int2 p = *reinterpret_cast<int2*>(&v);
    p.x = __shfl_xor_sync(0xFFFFFFFFu, p.x, m);
    p.y = __shfl_xor_sync(0xFFFFFFFFu, p.y, m);
    return *reinterpret_cast<double*>(&p);
}

__device__ __forceinline__ void load_stage_async(uint32_t smem_u, int stage,
                                                 int iBase, int jBase, int k0, int tid) {
    const uint32_t sbase = smem_u + stage * STAGE_BYTES;
#pragma unroll
    for (int it = 0; it < 8; ++it) {
        int idx = it * 256 + tid;       // 2048 x 16B units
        int row = idx >> 3;
        int sub = idx & 7;
        const __nv_bfloat16* src;
        uint32_t area;
        int lr;
        if (row < MT)           { lr = row;           src = g_Ht + (size_t)(iBase + lr) * NTOT; area = A_AREA; }
        else if (row < MT + NT) { lr = row - MT;      src = g_Ht + (size_t)(jBase + lr) * NTOT; area = BH_AREA; }
        else                    { lr = row - MT - NT; src = g_Lt + (size_t)(jBase + lr) * NTOT; area = BL_AREA; }
        uint32_t off = sw128((uint32_t)(lr * 128 + sub * 16));
        cp16(sbase + area + off, src + k0 + sub * 8);
    }
}

__global__ void __launch_bounds__(256) gram_mma_kernel() {
    extern __shared__ __align__(1024) char smem[];
    const uint32_t smem_u = smem_to_u32(smem);
    const int tid  = threadIdx.x;
    const int wid  = tid >> 5;
    const int lane = tid & 31;
    const int iBase = blockIdx.x * MT;
    const int jBase = blockIdx.y * NT;

    // 9-way split of 512 chunks: [512z/9, 512(z+1)/9) -> 56 or 57 chunks
    const int cstart = (TOTCHUNK * blockIdx.z) / NSPLIT;
    const int cend   = (TOTCHUNK * (blockIdx.z + 1)) / NSPLIT;
    const int nch    = cend - cstart;
    const int k0     = cstart * KC;

    // issue stage-0 fill first so the loss prologue overlaps its latency
    load_stage_async(smem_u, 0, iBase, jBase, k0, tid);
    cp_commit();

    // ---- fused loss reduction (~114 samples per CTA, hidden under cp.async) --
    {
        const int gbid = (int)(blockIdx.x + gridDim.x * (blockIdx.y + gridDim.y * blockIdx.z));
        const int s0 = (int)(((long long)NTOT * gbid) / NCTAS);
        const int s1 = (int)(((long long)NTOT * (gbid + 1)) / NCTAS);
        double lc = 0.0, lw = 0.0;
        for (int n = s0 + tid; n < s1; n += 256) {
            float s2 = 0.f, s4 = 0.f;
#pragma unroll
            for (int db = 0; db < 8; ++db) {
                s2 += g_ps2[db * NTOT + n];
                s4 += g_ps4[db * NTOT + n];
            }
            double d2 = (double)s2, d4 = (double)s4;
            lc += d2 * d2 - d4;
            lw += d4 - 2.0 * d2 + (double)D;
        }
#pragma unroll
        for (int o = 16; o > 0; o >>= 1) {
            lc += shfl_xor_d(lc, o);
            lw += shfl_xor_d(lw, o);
        }
        if (lane == 0) {
            atomicAdd(&g_corr, lc);   // REDG.f64, fire-and-forget
            atomicAdd(&g_whit, lw);
        }
    }

    const int m0 = (wid & 3) * 32;   // warp tile row within CTA tile
    const int n0 = (wid >> 2) * 32;  // warp tile col within CTA tile

    const uint32_t a_off0 = (uint32_t)((m0 + (lane & 15)) * 128 + (lane >> 4) * 16);
    const int bj   = ((lane & 16) >> 1) + (lane & 7);
    const uint32_t b_colb = (uint32_t)((lane & 8) * 2);
    const uint32_t b_off0 = (uint32_t)((n0 + bj) * 128) + b_colb;

    float accH[2][4][4];
    float accL[2][4][4];
#pragma unroll
    for (int mf = 0; mf < 2; ++mf)
#pragma unroll
        for (int nf = 0; nf < 4; ++nf)
#pragma unroll
            for (int e = 0; e < 4; ++e) { accH[mf][nf][e] = 0.f; accL[mf][nf][e] = 0.f; }

    for (int c = 0; c < nch; ++c) {
        if (c + 1 < nch) {
            load_stage_async(smem_u, (c + 1) & 1, iBase, jBase, k0 + (c + 1) * KC, tid);
            cp_commit();
            cp_wait<1>();
        } else {
            cp_wait<0>();
        }
        __syncthreads();

        const uint32_t sbase = smem_u + (c & 1) * STAGE_BYTES;
#pragma unroll
        for (int ks = 0; ks < KC / 16; ++ks) {
            const uint32_t kshift = (uint32_t)(ks * 32);
            uint32_t a[2][4], bh[2][4], bl[2][4];
#pragma unroll
            for (int mf = 0; mf < 2; ++mf)
                ldsm_x4(a[mf], sbase + A_AREA + sw128(a_off0 + (uint32_t)(mf * 2048) + kshift));
#pragma unroll
            for (int np = 0; np < 2; ++np) {
                uint32_t boff = b_off0 + (uint32_t)(np * 16 * 128) + kshift;
                ldsm_x4(bh[np], sbase + BH_AREA + sw128(boff));
                ldsm_x4(bl[np], sbase + BL_AREA + sw128(boff));
            }
#pragma unroll
            for (int mf = 0; mf < 2; ++mf)
#pragma unroll
                for (int np = 0; np < 2; ++np) {
                    mma_bf16(accH[mf][np * 2 + 0], a[mf], &bh[np][0]);
                    mma_bf16(accH[mf][np * 2 + 1], a[mf], &bh[np][2]);
                    mma_bf16(accL[mf][np * 2 + 0], a[mf], &bl[np][0]);
                    mma_bf16(accL[mf][np * 2 + 1], a[mf], &bl[np][2]);
                }
        }
        __syncthreads();
    }

    // epilogue: c frag element map (m16n8): e0:(g,2t) e1:(g,2t+1) e2:(g+8,2t) e3:(g+8,2t+1)
    const int g = lane >> 2;
    const int t = lane & 3;
#pragma unroll
    for (int mf = 0; mf < 2; ++mf)
#pragma unroll
        for (int nf = 0; nf < 4; ++nf)
#pragma unroll
            for (int e = 0; e < 4; ++e) {
                int i = iBase + m0 + mf * 16 + g + (e >> 1) * 8;
                int j = jBase + n0 + nf * 8 + 2 * t + (e & 1);
                float hh = accH[mf][nf][e];
                float hl = accL[mf][nf][e];
                atomicAdd(&g_c[i * D + j], hh + hl);
                atomicAdd(&g_c[j * D + i], hl);
            }
}

// ---------------- kernel 3: finalize ----------------
__global__ void __launch_bounds__(256) finalize_kernel(const float* __restrict__ kappa_p,
                                                       float* __restrict__ out) {
    int idx = blockIdx.x * blockDim.x + threadIdx.x;
    const float kappa = *kappa_p;
    const float invN  = 1.0f / (float)NTOT;
    if (idx < D * D) {
        int i = idx >> 9;
        int j = idx & (D - 1);
        float m = g_c[idx] * invN;
        out[idx] = (i == j) ? kappa * (m - 1.0f) : (1.0f - kappa) * m;
    }
    if (idx == 0) {
        double scale = 1.0 / ((double)NTOT * (double)D * (double)D);
        out[D * D]     = (float)(g_corr * scale);
        out[D * D + 1] = (float)(g_whit * scale);
    }
}

extern "C" void kernel_launch(void* const* d_in, const int* in_sizes, int n_in,
                              void* d_out, int out_size) {
    const float* x     = (const float*)d_in[0];
    const float* kappa = (const float*)d_in[1];
    float*       out   = (float*)d_out;

    cudaFuncSetAttribute(gram_mma_kernel, cudaFuncAttributeMaxDynamicSharedMemorySize, SMEM_BYTES);

    convert_kernel<<<dim3(NTOT / 64, D / 64), 256>>>(x);
    gram_mma_kernel<<<dim3(D / MT, D / NT, NSPLIT), 256, SMEM_BYTES>>>();
    finalize_kernel<<<(D * D + 255) / 256, 256>>>(kappa, out);
}

// round 17
// speedup vs baseline: 1.4596x; 1.4596x over previous
#include <cuda_runtime.h>
#include <cuda_bf16.h>
#include <cstdint>

// ---------------- problem constants ----------------
#define D      512
#define NTOT   32768            // 8*4096 samples
#define MT     128              // CTA gemm M tile
#define NT     64               // CTA gemm N tile
#define KC     64               // k per smem stage (64 bf16 = 128B rows)
#define NSPLIT 9                // 32 tiles * 9 = 288 CTAs <= 296 resident slots
#define TOTCHUNK (NTOT / KC)    // 512 total k-chunks

// ---------------- device scratch (no allocation) ----------------
__device__ __nv_bfloat16 g_Ht[(size_t)D * NTOT];   // 32 MB, K-major transposed hi
__device__ __nv_bfloat16 g_Lt[(size_t)D * NTOT];   // 32 MB, K-major transposed lo
__device__ float  g_c[D * D];                      // C = HH + HL + HL^T
__device__ float  g_ps2[8 * NTOT];                 // per-(dblock,sample) sum x^2
__device__ float  g_ps4[8 * NTOT];                 // per-(dblock,sample) sum x^4
__device__ double g_corr, g_whit;

__device__ __forceinline__ uint32_t smem_to_u32(const void* p) {
    uint32_t a;
    asm("{ .reg .u64 t; cvta.to.shared.u64 t, %1; cvt.u32.u64 %0, t; }" : "=r"(a) : "l"(p));
    return a;
}

// ---------------- kernel 1: transpose + hi/lo split + loss partials + zero ----
__global__ void __launch_bounds__(256) convert_kernel(const float* __restrict__ x) {
    __shared__ float tile[64][65];
    const int n0  = blockIdx.x * 64;
    const int db  = blockIdx.y;
    const int d0  = db * 64;
    const int tid = threadIdx.x;

    if (db == 0) {
        int base = blockIdx.x * 512 + tid;
        g_c[base] = 0.0f;
        g_c[base + 256] = 0.0f;
        if (blockIdx.x == 0 && tid == 0) { g_corr = 0.0; g_whit = 0.0; }
    }

    const int r  = tid >> 4;
    const int c4 = (tid & 15) * 4;
    float s2[4] = {0.f, 0.f, 0.f, 0.f};
    float s4[4] = {0.f, 0.f, 0.f, 0.f};
#pragma unroll
    for (int p = 0; p < 4; ++p) {
        int n = p * 16 + r;
        float4 v = *reinterpret_cast<const float4*>(x + (size_t)(n0 + n) * D + d0 + c4);
        tile[n][c4 + 0] = v.x; tile[n][c4 + 1] = v.y;
        tile[n][c4 + 2] = v.z; tile[n][c4 + 3] = v.w;
        float a = v.x * v.x, b = v.y * v.y, c = v.z * v.z, d = v.w * v.w;
        s2[p] += a + b + c + d;
        s4[p] += a * a + b * b + c * c + d * d;
    }
    __syncthreads();
    const int dd = tid >> 2;
    const int nb = (tid & 3) * 16;
    __align__(16) __nv_bfloat16 hi[16];
    __align__(16) __nv_bfloat16 lo[16];
#pragma unroll
    for (int u = 0; u < 16; ++u) {
        float v = tile[nb + u][dd];
        __nv_bfloat16 h = __float2bfloat16(v);
        hi[u] = h;
        lo[u] = __float2bfloat16(v - __bfloat162float(h));
    }
    size_t base = (size_t)(d0 + dd) * NTOT + (size_t)(n0 + nb);
    *reinterpret_cast<uint4*>(&g_Ht[base])     = *reinterpret_cast<uint4*>(hi);
    *reinterpret_cast<uint4*>(&g_Ht[base + 8]) = *reinterpret_cast<uint4*>(hi + 8);
    *reinterpret_cast<uint4*>(&g_Lt[base])     = *reinterpret_cast<uint4*>(lo);
    *reinterpret_cast<uint4*>(&g_Lt[base + 8]) = *reinterpret_cast<uint4*>(lo + 8);

#pragma unroll
    for (int o = 8; o > 0; o >>= 1)
#pragma unroll
        for (int p = 0; p < 4; ++p) {
            s2[p] += __shfl_xor_sync(0xFFFFFFFFu, s2[p], o);
            s4[p] += __shfl_xor_sync(0xFFFFFFFFu, s4[p], o);
        }
    if ((tid & 15) == 0) {
#pragma unroll
        for (int p = 0; p < 4; ++p) {
            int n = n0 + p * 16 + r;
            g_ps2[db * NTOT + n] = s2[p];
            g_ps4[db * NTOT + n] = s4[p];
        }
    }
}

// ---------------- kernel 2: loss reduction (parallel) ----------------
__global__ void __launch_bounds__(256) loss_reduce_kernel() {
    const int n = blockIdx.x * 256 + threadIdx.x;
    float s2 = 0.f, s4 = 0.f;
#pragma unroll
    for (int db = 0; db < 8; ++db) {
        s2 += g_ps2[db * NTOT + n];
        s4 += g_ps4[db * NTOT + n];
    }
    double d2 = (double)s2, d4 = (double)s4;
    double lc = d2 * d2 - d4;
    double lw = d4 - 2.0 * d2 + (double)D;

    __shared__ double sc[256], sw2[256];
    sc[threadIdx.x] = lc; sw2[threadIdx.x] = lw;
    __syncthreads();
    for (int o = 128; o > 0; o >>= 1) {
        if (threadIdx.x < o) {
            sc[threadIdx.x]  += sc[threadIdx.x + o];
            sw2[threadIdx.x] += sw2[threadIdx.x + o];
        }
        __syncthreads();
    }
    if (threadIdx.x == 0) {
        atomicAdd(&g_corr, sc[0]);
        atomicAdd(&g_whit, sw2[0]);
    }
}

// ---------------- kernel 3: mma.sync gram (9-way split-K, all-resident) ------
// Per CTA: C_tile(i,j) 128x64.  HH = H_i^T H_j, HL = H_i^T L_j  (fp32 accum)
// Epilogue: g_c[i][j] += HH + HL ;  g_c[j][i] += HL
#define STAGE_BYTES 32768
#define A_AREA  0
#define BH_AREA 16384
#define BL_AREA 24576
#define SMEM_BYTES (2 * STAGE_BYTES)

__device__ __forceinline__ uint32_t sw128(uint32_t off) {
    return off ^ ((off >> 3) & 0x70);
}
__device__ __forceinline__ void cp16(uint32_t saddr, const void* gaddr) {
    asm volatile("cp.async.cg.shared.global [%0], [%1], 16;" :: "r"(saddr), "l"(gaddr));
}
__device__ __forceinline__ void cp_commit() {
    asm volatile("cp.async.commit_group;" ::: "memory");
}
template <int N>
__device__ __forceinline__ void cp_wait() {
    asm volatile("cp.async.wait_group %0;" :: "n"(N) : "memory");
}
__device__ __forceinline__ void ldsm_x4(uint32_t* r, uint32_t addr) {
    asm volatile("ldmatrix.sync.aligned.m8n8.x4.shared.b16 {%0,%1,%2,%3}, [%4];"
                 : "=r"(r[0]), "=r"(r[1]), "=r"(r[2]), "=r"(r[3]) : "r"(addr));
}
__device__ __forceinline__ void mma_bf16(float* c, const uint32_t* a, const uint32_t* b) {
    asm volatile(
        "mma.sync.aligned.m16n8k16.row.col.f32.bf16.bf16.f32 "
        "{%0,%1,%2,%3}, {%4,%5,%6,%7}, {%8,%9}, {%0,%1,%2,%3};"
        : "+f"(c[0]), "+f"(c[1]), "+f"(c[2]), "+f"(c[3])
        : "r"(a[0]), "r"(a[1]), "r"(a[2]), "r"(a[3]), "r"(b[0]), "r"(b[1]));
}

__device__ __forceinline__ void load_stage_async(uint32_t smem_u, int stage,
                                                 int iBase, int jBase, int k0, int tid) {
    const uint32_t sbase = smem_u + stage * STAGE_BYTES;
#pragma unroll
    for (int it = 0; it < 8; ++it) {
        int idx = it * 256 + tid;       // 2048 x 16B units
        int row = idx >> 3;
        int sub = idx & 7;
        const __nv_bfloat16* src;
        uint32_t area;
        int lr;
        if (row < MT)           { lr = row;           src = g_Ht + (size_t)(iBase + lr) * NTOT; area = A_AREA; }
        else if (row < MT + NT) { lr = row - MT;      src = g_Ht + (size_t)(jBase + lr) * NTOT; area = BH_AREA; }
        else                    { lr = row - MT - NT; src = g_Lt + (size_t)(jBase + lr) * NTOT; area = BL_AREA; }
        uint32_t off = sw128((uint32_t)(lr * 128 + sub * 16));
        cp16(sbase + area + off, src + k0 + sub * 8);
    }
}

__global__ void __launch_bounds__(256) gram_mma_kernel() {
    extern __shared__ __align__(1024) char smem[];
    const uint32_t smem_u = smem_to_u32(smem);
    const int tid  = threadIdx.x;
    const int wid  = tid >> 5;
    const int lane = tid & 31;
    const int iBase = blockIdx.x * MT;
    const int jBase = blockIdx.y * NT;

    // 9-way split of 512 chunks: [512z/9, 512(z+1)/9) -> 56 or 57 chunks
    const int cstart = (TOTCHUNK * blockIdx.z) / NSPLIT;
    const int cend   = (TOTCHUNK * (blockIdx.z + 1)) / NSPLIT;
    const int nch    = cend - cstart;
    const int k0     = cstart * KC;

    const int m0 = (wid & 3) * 32;   // warp tile row within CTA tile
    const int n0 = (wid >> 2) * 32;  // warp tile col within CTA tile

    const uint32_t a_off0 = (uint32_t)((m0 + (lane & 15)) * 128 + (lane >> 4) * 16);
    const int bj   = ((lane & 16) >> 1) + (lane & 7);
    const uint32_t b_colb = (uint32_t)((lane & 8) * 2);
    const uint32_t b_off0 = (uint32_t)((n0 + bj) * 128) + b_colb;

    float accH[2][4][4];
    float accL[2][4][4];
#pragma unroll
    for (int mf = 0; mf < 2; ++mf)
#pragma unroll
        for (int nf = 0; nf < 4; ++nf)
#pragma unroll
            for (int e = 0; e < 4; ++e) { accH[mf][nf][e] = 0.f; accL[mf][nf][e] = 0.f; }

    load_stage_async(smem_u, 0, iBase, jBase, k0, tid);
    cp_commit();

    for (int c = 0; c < nch; ++c) {
        if (c + 1 < nch) {
            load_stage_async(smem_u, (c + 1) & 1, iBase, jBase, k0 + (c + 1) * KC, tid);
            cp_commit();
            cp_wait<1>();
        } else {
            cp_wait<0>();
        }
        __syncthreads();

        const uint32_t sbase = smem_u + (c & 1) * STAGE_BYTES;
#pragma unroll
        for (int ks = 0; ks < KC / 16; ++ks) {
            const uint32_t kshift = (uint32_t)(ks * 32);
            uint32_t a[2][4], bh[2][4], bl[2][4];
#pragma unroll
            for (int mf = 0; mf < 2; ++mf)
                ldsm_x4(a[mf], sbase + A_AREA + sw128(a_off0 + (uint32_t)(mf * 2048) + kshift));
#pragma unroll
            for (int np = 0; np < 2; ++np) {
                uint32_t boff = b_off0 + (uint32_t)(np * 16 * 128) + kshift;
                ldsm_x4(bh[np], sbase + BH_AREA + sw128(boff));
                ldsm_x4(bl[np], sbase + BL_AREA + sw128(boff));
            }
#pragma unroll
            for (int mf = 0; mf < 2; ++mf)
#pragma unroll
                for (int np = 0; np < 2; ++np) {
                    mma_bf16(accH[mf][np * 2 + 0], a[mf], &bh[np][0]);
                    mma_bf16(accH[mf][np * 2 + 1], a[mf], &bh[np][2]);
                    mma_bf16(accL[mf][np * 2 + 0], a[mf], &bl[np][0]);
                    mma_bf16(accL[mf][np * 2 + 1], a[mf], &bl[np][2]);
                }
        }
        __syncthreads();
    }

    // epilogue: c frag element map (m16n8): e0:(g,2t) e1:(g,2t+1) e2:(g+8,2t) e3:(g+8,2t+1)
    const int g = lane >> 2;
    const int t = lane & 3;
#pragma unroll
    for (int mf = 0; mf < 2; ++mf)
#pragma unroll
        for (int nf = 0; nf < 4; ++nf)
#pragma unroll
            for (int e = 0; e < 4; ++e) {
                int i = iBase + m0 + mf * 16 + g + (e >> 1) * 8;
                int j = jBase + n0 + nf * 8 + 2 * t + (e & 1);
                float hh = accH[mf][nf][e];
                float hl = accL[mf][nf][e];
                atomicAdd(&g_c[i * D + j], hh + hl);
                atomicAdd(&g_c[j * D + i], hl);
            }
}

// ---------------- kernel 4: finalize ----------------
__global__ void __launch_bounds__(256) finalize_kernel(const float* __restrict__ kappa_p,
                                                       float* __restrict__ out) {
    int idx = blockIdx.x * blockDim.x + threadIdx.x;
    const float kappa = *kappa_p;
    const float invN  = 1.0f / (float)NTOT;
    if (idx < D * D) {
        int i = idx >> 9;
        int j = idx & (D - 1);
        float m = g_c[idx] * invN;
        out[idx] = (i == j) ? kappa * (m - 1.0f) : (1.0f - kappa) * m;
    }
    if (idx == 0) {
        double scale = 1.0 / ((double)NTOT * (double)D * (double)D);
        out[D * D]     = (float)(g_corr * scale);
        out[D * D + 1] = (float)(g_whit * scale);
    }
}

extern "C" void kernel_launch(void* const* d_in, const int* in_sizes, int n_in,
                              void* d_out, int out_size) {
    const float* x     = (const float*)d_in[0];
    const float* kappa = (const float*)d_in[1];
    float*       out   = (float*)d_out;

    cudaFuncSetAttribute(gram_mma_kernel, cudaFuncAttributeMaxDynamicSharedMemorySize, SMEM_BYTES);

    convert_kernel<<<dim3(NTOT / 64, D / 64), 256>>>(x);
    loss_reduce_kernel<<<NTOT / 256, 256>>>();
    gram_mma_kernel<<<dim3(D / MT, D / NT, NSPLIT), 256, SMEM_BYTES>>>();
    finalize_kernel<<<(D * D + 255) / 256, 256>>>(kappa, out);
}